// round 12
// baseline (speedup 1.0000x reference)
#include <cuda_runtime.h>
#include <cstdint>
#include <cstddef>

// Problem constants
#define Bsz 16
#define Ssz 512
#define Nent 64
#define Hdim 768
#define HH 384          // H/2
#define ET 9
#define RT 10
#define NPAIR 2016      // 64*63/2
#define MS (Bsz*Ssz)    // 8192
#define ME (Bsz*Nent)   // 1024
#define PAIRN (2*Hdim)  // 1536
#define ZPAIR 4         // split-K factor, pair GEMM
#define K2 (Hdim/2)     // 384 packed k-pairs

// Scratch (static device arrays — allocation-free rule)
__device__ float g_hidden[(size_t)MS * HH];            // relu(seq@W1e+b1e)
__device__ float g_pK[ZPAIR][(size_t)ME * PAIRN];      // pair GEMM split-K partials
__device__ float2 g_pA2[(size_t)Bsz * K2 * Nent];      // pA+b1r, k-paired [b][k2][n]
__device__ float2 g_pB2[(size_t)Bsz * K2 * Nent];      // pB, k-paired [b][k2][n]
__device__ float2 g_Wq[(size_t)K2 * 12];               // 0.5*W2r, k-paired, padded 12
__device__ int   g_pairs[2048 * 2];                    // pair index table

// ===========================================================================
// Packed fp32x2 + cp.async helpers (base-ISA PTX)
// ===========================================================================
__device__ __forceinline__ void ffma2(unsigned long long& d,
                                      unsigned long long a,
                                      unsigned long long b) {
    asm("fma.rn.f32x2 %0, %1, %2, %0;" : "+l"(d) : "l"(a), "l"(b));
}
__device__ __forceinline__ unsigned long long fadd2v(unsigned long long a,
                                                     unsigned long long b) {
    unsigned long long d;
    asm("add.rn.f32x2 %0, %1, %2;" : "=l"(d) : "l"(a), "l"(b));
    return d;
}
__device__ __forceinline__ unsigned long long dup2(float x) {
    unsigned long long r; unsigned u = __float_as_uint(x);
    asm("mov.b64 %0, {%1, %1};" : "=l"(r) : "r"(u));
    return r;
}
__device__ __forceinline__ float2 unpack2(unsigned long long v) {
    unsigned lo, hi;
    asm("mov.b64 {%0, %1}, %2;" : "=r"(lo), "=r"(hi) : "l"(v));
    return make_float2(__uint_as_float(lo), __uint_as_float(hi));
}
__device__ __forceinline__ uint32_t smem_u32(const void* p) {
    uint32_t a;
    asm("{ .reg .u64 t; cvta.to.shared.u64 t, %1; cvt.u32.u64 %0, t; }"
        : "=r"(a) : "l"(p));
    return a;
}
__device__ __forceinline__ void cp_async16(uint32_t saddr, const void* gaddr) {
    asm volatile("cp.async.cg.shared.global [%0], [%1], 16;"
                 :: "r"(saddr), "l"(gaddr) : "memory");
}
#define CP_COMMIT() asm volatile("cp.async.commit_group;" ::: "memory")
#define CP_WAIT0()  asm volatile("cp.async.wait_group 0;" ::: "memory")

// ===========================================================================
// Merged FFMA2 SGEMM megakernel (verified engine — UNTOUCHED since R8):
//   class E (bid%3==0): hidden = relu(seq[8192,768] @ W1e[768,384] + b1e)
//   class P (else):     pK[z] = ER[1024,768] @ [W1r_top|W1r_bot] (z-th K slice)
// ===========================================================================
#define GTM 64
#define GTN 128
#define GTK 32
#define ASTRIDE 68
#define ASTAGE (GTK*ASTRIDE)
#define BSTAGE (GTK*GTN)
#define GEMM_SMEM ((2*ASTAGE + 2*BSTAGE) * 4)   // 50176 bytes

__global__ __launch_bounds__(128) void gemm_mega(
    const float* __restrict__ seq,  const float* __restrict__ W1e,
    const float* __restrict__ b1e,  float* __restrict__ hidden,
    const float* __restrict__ ER,   const float* __restrict__ W1r,
    float* __restrict__ pK)
{
    extern __shared__ float sm[];
    float* smA = sm;
    float* smB = sm + 2 * ASTAGE;

    const int tid = threadIdx.x;
    const int wid = tid >> 5, lane = tid & 31;
    const int lm = lane >> 2;
    const int ln = lane & 3;
    const int col0 = wid * 32 + ln * 8;

    const int bid = blockIdx.x;
    const bool isEnt = (bid % 3) == 0;

    const float* Ab;  int lda;
    const float* Bb;  int ldb;
    float* Cb;        int ldc;
    int CH, bm, colg0;

    if (isEnt) {
        int id = bid / 3;
        int nx = id % 3, my = id / 3;
        bm = my * GTM; colg0 = nx * GTN;
        lda = Hdim; ldb = HH; ldc = HH;
        Ab = seq + (size_t)bm * lda;
        Bb = W1e + colg0;
        Cb = hidden;
        CH = Hdim / GTK;
    } else {
        int id = bid - 1 - (bid - 1) / 3;
        int z = id / 192;
        int rem = id % 192;
        int nx = rem % 12, my = rem / 12;
        bm = my * GTM; colg0 = nx * GTN;
        lda = Hdim; ldb = Hdim; ldc = PAIRN;
        const int Kper = Hdim / ZPAIR;
        Ab = ER + (size_t)z * Kper + (size_t)bm * lda;
        int bn = colg0;
        const float* Bsel = W1r;
        if (bn >= Hdim) { Bsel = W1r + (size_t)Hdim * Hdim; bn -= Hdim; }
        Bb = Bsel + (size_t)z * Kper * ldb + bn;
        Cb = pK + (size_t)z * ((size_t)ME * PAIRN);
        CH = Kper / GTK;
    }

    unsigned long long acc[4][8];
#pragma unroll
    for (int r = 0; r < 4; r++)
#pragma unroll
        for (int c = 0; c < 8; c++) acc[r][c] = 0ull;

    float4 ra[4];

#define LDG_A(k0) do { \
    _Pragma("unroll") \
    for (int q = 0; q < 4; q++) { \
        int idx = q * 128 + tid; \
        int m = idx >> 3, kq = (idx & 7) << 2; \
        ra[q] = *(const float4*)(Ab + (size_t)m * lda + (k0) + kq); \
    } \
} while (0)
#define STS_A(dst) do { \
    _Pragma("unroll") \
    for (int q = 0; q < 4; q++) { \
        int idx = q * 128 + tid; \
        int m = idx >> 3, kq = (idx & 7) << 2; \
        int ms = m ^ kq; \
        (dst)[(kq + 0) * ASTRIDE + ms] = ra[q].x; \
        (dst)[(kq + 1) * ASTRIDE + ms] = ra[q].y; \
        (dst)[(kq + 2) * ASTRIDE + ms] = ra[q].z; \
        (dst)[(kq + 3) * ASTRIDE + ms] = ra[q].w; \
    } \
} while (0)
#define CPA_B(k0, stB) do { \
    uint32_t sb = smem_u32(smB + (stB) * BSTAGE) + (uint32_t)tid * 16u; \
    _Pragma("unroll") \
    for (int q = 0; q < 8; q++) { \
        int idx = q * 128 + tid; \
        int k = idx >> 5, c4 = (idx & 31) << 2; \
        cp_async16(sb + q * 2048u, Bb + (size_t)((k0) + k) * ldb + c4); \
    } \
    CP_COMMIT(); \
} while (0)

    CPA_B(0, 0);
    LDG_A(0);
    STS_A(smA);
    CP_WAIT0();
    __syncthreads();

    for (int c = 0; c < CH; c++) {
        const int st = c & 1;
        const int nx2 = st ^ 1;
        if (c + 1 < CH) {
            CPA_B((c + 1) * GTK, nx2);
            LDG_A((c + 1) * GTK);
        }

        const float* Asm = smA + st * ASTAGE;
        const float* Bsm = smB + st * BSTAGE;
#pragma unroll
        for (int k = 0; k < GTK; k++) {
            const int sw = k & 28;
            ulonglong2 ap0 = *(const ulonglong2*)&Asm[k * ASTRIDE + ((4 * lm) ^ sw)];
            ulonglong2 ap1 = *(const ulonglong2*)&Asm[k * ASTRIDE + (32 + ((4 * lm) ^ sw))];
            float4 b0 = *(const float4*)&Bsm[k * GTN + col0];
            float4 b1 = *(const float4*)&Bsm[k * GTN + col0 + 4];
            unsigned long long bd[8];
            bd[0] = dup2(b0.x); bd[1] = dup2(b0.y); bd[2] = dup2(b0.z); bd[3] = dup2(b0.w);
            bd[4] = dup2(b1.x); bd[5] = dup2(b1.y); bd[6] = dup2(b1.z); bd[7] = dup2(b1.w);
            unsigned long long ap[4] = {ap0.x, ap0.y, ap1.x, ap1.y};
#pragma unroll
            for (int r = 0; r < 4; r++)
#pragma unroll
                for (int cc = 0; cc < 8; cc++)
                    ffma2(acc[r][cc], ap[r], bd[cc]);
        }

        if (c + 1 < CH) STS_A(smA + nx2 * ASTAGE);
        CP_WAIT0();
        __syncthreads();
    }

    const int colg = colg0 + col0;
    float bb[8] = {0, 0, 0, 0, 0, 0, 0, 0};
    if (isEnt) {
        float4 t0 = *(const float4*)(b1e + colg);
        float4 t1 = *(const float4*)(b1e + colg + 4);
        bb[0] = t0.x; bb[1] = t0.y; bb[2] = t0.z; bb[3] = t0.w;
        bb[4] = t1.x; bb[5] = t1.y; bb[6] = t1.z; bb[7] = t1.w;
    }
#pragma unroll
    for (int rp = 0; rp < 4; rp++) {
        int r0 = (rp < 2) ? (4 * lm + 2 * rp) : (32 + 4 * lm + 2 * (rp - 2));
        float lo[8], hi[8];
#pragma unroll
        for (int cc = 0; cc < 8; cc++) {
            float2 v = unpack2(acc[rp][cc]);
            lo[cc] = v.x + bb[cc];
            hi[cc] = v.y + bb[cc];
        }
        if (isEnt) {
#pragma unroll
            for (int q = 0; q < 8; q++) {
                lo[q] = fmaxf(lo[q], 0.f);
                hi[q] = fmaxf(hi[q], 0.f);
            }
        }
        float* C0 = Cb + (size_t)(bm + r0) * ldc + colg;
        float* C1 = Cb + (size_t)(bm + r0 + 1) * ldc + colg;
        *(float4*)C0 = make_float4(lo[0], lo[1], lo[2], lo[3]);
        *(float4*)(C0 + 4) = make_float4(lo[4], lo[5], lo[6], lo[7]);
        *(float4*)C1 = make_float4(hi[0], hi[1], hi[2], hi[3]);
        *(float4*)(C1 + 4) = make_float4(hi[4], hi[5], hi[6], hi[7]);
    }
#undef LDG_A
#undef STS_A
#undef CPA_B
}

// ===========================================================================
// Launch 3: combine+transpose+k-pack | pair-table | Wq pack.
//  combine: v = sum_z pK[z] (+b1r for k'<768), k-paired into g_pA2/g_pB2.
// ===========================================================================
#define CTBLKS ((PAIRN / 32) * (ME / 32))    // 1536
#define PTBLKS 8                             // 8*256 = 2048 >= NPAIR
#define WQBLKS 18                            // 18*256 = 4608 = 384*12

__global__ __launch_bounds__(256) void combine_kernel(
    const float* __restrict__ b1r, const float* __restrict__ W2r)
{
    __shared__ float t[32][33];
    const int tid = threadIdx.x;

    if (blockIdx.x < CTBLKS) {
        const int cb = blockIdx.x;
        const int kb = (cb % (PAIRN / 32)) * 32;     // k' base
        const int eb = (cb / (PAIRN / 32)) * 32;     // entity-row base
        const int tx = tid & 31;
        const int ty = tid >> 5;                      // 0..7

#pragma unroll
        for (int s = 0; s < 4; s++) {
            int e = eb + ty + s * 8;
            size_t off = (size_t)e * PAIRN + kb + tx;
            float v = g_pK[0][off];
#pragma unroll
            for (int zz = 1; zz < ZPAIR; zz++) v += g_pK[zz][off];
            t[ty + s * 8][tx] = v;
        }
        __syncthreads();

        // thread owns k' = kb + ty*4 + {0..3} at entity e = eb + tx
        const int b = eb >> 6;
        const int n = (eb & 63) + tx;      // tx<32, eb%64 in {0,32}
        float v[4];
#pragma unroll
        for (int s = 0; s < 4; s++) v[s] = t[tx][ty * 4 + s];

        const int kk0 = kb + ty * 4;
        if (kk0 < Hdim) {
#pragma unroll
            for (int s = 0; s < 4; s++) v[s] += b1r[kk0 + s];
            const int k2 = kk0 >> 1;
            g_pA2[((size_t)b * K2 + k2) * Nent + n]     = make_float2(v[0], v[1]);
            g_pA2[((size_t)b * K2 + k2 + 1) * Nent + n] = make_float2(v[2], v[3]);
        } else {
            const int k2 = (kk0 - Hdim) >> 1;
            g_pB2[((size_t)b * K2 + k2) * Nent + n]     = make_float2(v[0], v[1]);
            g_pB2[((size_t)b * K2 + k2 + 1) * Nent + n] = make_float2(v[2], v[3]);
        }
    } else if (blockIdx.x < CTBLKS + PTBLKS) {
        int p = (blockIdx.x - CTBLKS) * 256 + tid;
        if (p < NPAIR) {
            int rem = p, i = 0;
            while (rem >= (Nent - 1) - i) { rem -= (Nent - 1) - i; i++; }
            g_pairs[p * 2]     = i;
            g_pairs[p * 2 + 1] = i + 1 + rem;
        }
    } else {
        // Wq[k2][c] = {0.5*W(2k2,c), 0.5*W(2k2+1,c)}, c<10 else 0
        int idx = (blockIdx.x - CTBLKS - PTBLKS) * 256 + tid;
        if (idx < K2 * 12) {
            int k2 = idx / 12, c = idx % 12;
            float w0 = (c < RT) ? 0.5f * W2r[(2 * k2) * RT + c] : 0.f;
            float w1 = (c < RT) ? 0.5f * W2r[(2 * k2 + 1) * RT + c] : 0.f;
            g_Wq[idx] = make_float2(w0, w1);
        }
    }
}

// ===========================================================================
// Span mean pooling, fixed 16-iteration predicated loop.
// ===========================================================================
__global__ __launch_bounds__(192) void span_pool_kernel(
    const float4* __restrict__ seq4, const int* __restrict__ spans,
    float4* __restrict__ er4)
{
    const int bn = blockIdx.x;
    const int b = bn >> 6;
    const int s0 = spans[bn * 2];
    const int s1 = spans[bn * 2 + 1];
    int cnt = s1 - s0; if (cnt < 1) cnt = 1;
    const float inv = 1.f / (float)cnt;
    const float4* base = seq4 + (size_t)b * Ssz * (Hdim / 4) + threadIdx.x;

    float4 acc = make_float4(0.f, 0.f, 0.f, 0.f);
#pragma unroll
    for (int q = 0; q < 16; q++) {
        int s = s0 + q;
        float4 v = base[(size_t)s * (Hdim / 4)];
        if (s < s1) { acc.x += v.x; acc.y += v.y; acc.z += v.z; acc.w += v.w; }
    }
    acc.x *= inv; acc.y *= inv; acc.z *= inv; acc.w *= inv;
    er4[(size_t)bn * (Hdim / 4) + threadIdx.x] = acc;
}

// ===========================================================================
// Launch 4: relation (blockIdx.x < 16) | entity_logits (blockIdx.x >= 16).
// Relation: thread per pair, k-paired smem staging, packed relu (x+|x| with
// half-scaled W), 12 packed accumulators holding {even-k, odd-k} sums.
// EL: 4 rows per 128-thread block (warp per row).
// Shared memory is a raw union (relation needs 35.8 KB, EL 13.8 KB).
// ===========================================================================
#define RELXB 16
#define ELXB 128                       // (144-16) x-slots; ids = (x-16)*16+y
#define RK2T 32                        // k2-rows per staged tile (=64 k)

__global__ __launch_bounds__(128) void rel_el_kernel(
    const float* __restrict__ W2e, const float* __restrict__ b2e,
    const float* __restrict__ b2r,
    float* __restrict__ el_out, float* __restrict__ rl_out)
{
    __shared__ __align__(16) char smraw[RK2T * Nent * 8 * 2 + RK2T * 12 * 8];
    const int tid = threadIdx.x;

    if (blockIdx.x < RELXB) {
        // ---------------- relation ----------------
        unsigned long long* sA = (unsigned long long*)smraw;                // [32][64]
        unsigned long long* sB = sA + RK2T * Nent;                          // [32][64]
        unsigned long long* sW = sB + RK2T * Nent;                          // [32][12]

        const int b = blockIdx.y;
        const int p = blockIdx.x * 128 + tid;
        const bool act = (p < NPAIR);
        const int pc = act ? p : 0;
        const int i = g_pairs[pc * 2];
        const int j = g_pairs[pc * 2 + 1];

        const float2* A2 = g_pA2 + (size_t)b * K2 * Nent;
        const float2* B2 = g_pB2 + (size_t)b * K2 * Nent;

        unsigned long long acc[12];
#pragma unroll
        for (int c = 0; c < 12; c++) acc[c] = 0ull;

        const unsigned long long ABSM = 0x7FFFFFFF7FFFFFFFull;

        for (int kt = 0; kt < K2; kt += RK2T) {
            __syncthreads();
            // stage A2/B2 tiles: 2048 float2 = 1024 float4 each, 8/thread
#pragma unroll
            for (int q = 0; q < 8; q++) {
                int idx = q * 128 + tid;             // float4 index (2 float2)
                ((float4*)sA)[idx] = ((const float4*)(A2 + (size_t)kt * Nent))[idx];
                ((float4*)sB)[idx] = ((const float4*)(B2 + (size_t)kt * Nent))[idx];
            }
            // stage Wq tile: 384 float2 = 192 float4
#pragma unroll
            for (int q = 0; q < 2; q++) {
                int idx = q * 128 + tid;
                if (idx < RK2T * 6)
                    ((float4*)sW)[idx] = ((const float4*)(g_Wq + (size_t)kt * 12))[idx];
            }
            __syncthreads();

#pragma unroll 4
            for (int k2 = 0; k2 < RK2T; k2++) {
                unsigned long long a = sA[k2 * Nent + i];
                unsigned long long bq = sB[k2 * Nent + j];
                unsigned long long x = fadd2v(a, bq);
                unsigned long long h2 = fadd2v(x, x & ABSM);   // 2*relu packed
                const unsigned long long* w = &sW[k2 * 12];
#pragma unroll
                for (int c = 0; c < 12; c++)
                    ffma2(acc[c], h2, w[c]);
            }
        }

        if (act) {
            float* dst = rl_out + (size_t)(b * NPAIR + p) * RT;
#pragma unroll
            for (int c = 0; c < RT; c++) {
                float2 v = unpack2(acc[c]);
                dst[c] = v.x + v.y + b2r[c];
            }
        }
    } else {
        // ---------------- entity logits ----------------
        float* W2s = (float*)smraw;                  // HH*ET = 13.8 KB
        for (int i = tid; i < HH * ET; i += 128) W2s[i] = W2e[i];
        __syncthreads();

        const int id = (blockIdx.x - RELXB) * Bsz + blockIdx.y;   // 0..2047
        const int warp = tid >> 5, lane = tid & 31;
        const int row = id * 4 + warp;               // 0..8191
        const float* hrow = g_hidden + (size_t)row * HH;

        float acc[ET];
#pragma unroll
        for (int c = 0; c < ET; c++) acc[c] = 0.f;

#pragma unroll
        for (int kk = 0; kk < HH / 32; kk++) {
            int k = kk * 32 + lane;
            float h = hrow[k];
            const float* w = &W2s[k * ET];
#pragma unroll
            for (int c = 0; c < ET; c++) acc[c] += h * w[c];
        }
#pragma unroll
        for (int c = 0; c < ET; c++)
#pragma unroll
            for (int off = 16; off > 0; off >>= 1)
                acc[c] += __shfl_down_sync(0xffffffffu, acc[c], off);

        if (lane == 0) {
            float* o = el_out + (size_t)row * ET;
#pragma unroll
            for (int c = 0; c < ET; c++) o[c] = acc[c] + b2e[c];
        }
    }
}

// ===========================================================================
extern "C" void kernel_launch(void* const* d_in, const int* in_sizes, int n_in,
                              void* d_out, int out_size)
{
    const float* seq   = (const float*)d_in[0];
    const int*   spans = (const int*)d_in[2];
    const float* W1e   = (const float*)d_in[3];
    const float* b1e   = (const float*)d_in[4];
    const float* W2e   = (const float*)d_in[5];
    const float* b2e   = (const float*)d_in[6];
    const float* W1r   = (const float*)d_in[7];
    const float* b1r   = (const float*)d_in[8];
    const float* W2r   = (const float*)d_in[9];
    const float* b2r   = (const float*)d_in[10];

    float* out = (float*)d_out;
    float* EL = out;                                   // [16,512,9]
    float* ER = out + (size_t)MS * ET;                 // [16,64,768]
    float* RL = ER + (size_t)ME * Hdim;                // [16,2016,10]

    void *p_hidden, *p_pK;
    cudaGetSymbolAddress(&p_hidden, g_hidden);
    cudaGetSymbolAddress(&p_pK, g_pK);

    cudaFuncSetAttribute(gemm_mega,
                         cudaFuncAttributeMaxDynamicSharedMemorySize, GEMM_SMEM);

    // 1) entity_repr (output + input of pair GEMM)
    span_pool_kernel<<<Bsz * Nent, 192>>>((const float4*)seq, spans, (float4*)ER);

    // 2) merged GEMMs: hidden (entity) + pK[z] (pair split-K=4), 1152 CTAs
    gemm_mega<<<1152, 128, GEMM_SMEM>>>(
        seq, W1e, b1e, (float*)p_hidden, ER, W1r, (float*)p_pK);

    // 3) combine+k-pack | pair table | Wq pack
    combine_kernel<<<CTBLKS + PTBLKS + WQBLKS, 256>>>(b1r, W2r);

    // 4) relation (x<16) overlapped with entity_logits (x>=16)
    rel_el_kernel<<<dim3(RELXB + ELXB, Bsz), 128>>>(W2e, b2e, b2r, EL, RL);
}

// round 13
// speedup vs baseline: 1.1162x; 1.1162x over previous
#include <cuda_runtime.h>
#include <cstdint>
#include <cstddef>

// Problem constants
#define Bsz 16
#define Ssz 512
#define Nent 64
#define Hdim 768
#define HH 384          // H/2
#define ET 9
#define RT 10
#define NPAIR 2016      // 64*63/2
#define MS (Bsz*Ssz)    // 8192
#define ME (Bsz*Nent)   // 1024
#define PAIRN (2*Hdim)  // 1536
#define ZPAIR 4         // split-K factor, pair GEMM
#define K2 (Hdim/2)     // 384 packed k-pairs

// Scratch (static device arrays — allocation-free rule)
__device__ float g_hidden[(size_t)MS * HH];            // relu(seq@W1e+b1e)
__device__ float g_pK[ZPAIR][(size_t)ME * PAIRN];      // pair GEMM split-K partials
__device__ float2 g_pA2[(size_t)Bsz * K2 * Nent];      // pA+b1r, k-paired [b][k2][n]
__device__ float2 g_pB2[(size_t)Bsz * K2 * Nent];      // pB, k-paired [b][k2][n]
__device__ float2 g_Wq[(size_t)K2 * 12];               // 0.5*W2r, k-paired, padded 12
__device__ int   g_pairs[2048 * 2];                    // pair index table

// ===========================================================================
// Packed fp32x2 + cp.async helpers (base-ISA PTX)
// ===========================================================================
__device__ __forceinline__ void ffma2(unsigned long long& d,
                                      unsigned long long a,
                                      unsigned long long b) {
    asm("fma.rn.f32x2 %0, %1, %2, %0;" : "+l"(d) : "l"(a), "l"(b));
}
__device__ __forceinline__ unsigned long long fadd2v(unsigned long long a,
                                                     unsigned long long b) {
    unsigned long long d;
    asm("add.rn.f32x2 %0, %1, %2;" : "=l"(d) : "l"(a), "l"(b));
    return d;
}
__device__ __forceinline__ unsigned long long dup2(float x) {
    unsigned long long r; unsigned u = __float_as_uint(x);
    asm("mov.b64 %0, {%1, %1};" : "=l"(r) : "r"(u));
    return r;
}
__device__ __forceinline__ float2 unpack2(unsigned long long v) {
    unsigned lo, hi;
    asm("mov.b64 {%0, %1}, %2;" : "=r"(lo), "=r"(hi) : "l"(v));
    return make_float2(__uint_as_float(lo), __uint_as_float(hi));
}
__device__ __forceinline__ uint32_t smem_u32(const void* p) {
    uint32_t a;
    asm("{ .reg .u64 t; cvta.to.shared.u64 t, %1; cvt.u32.u64 %0, t; }"
        : "=r"(a) : "l"(p));
    return a;
}
__device__ __forceinline__ void cp_async16(uint32_t saddr, const void* gaddr) {
    asm volatile("cp.async.cg.shared.global [%0], [%1], 16;"
                 :: "r"(saddr), "l"(gaddr) : "memory");
}
#define CP_COMMIT() asm volatile("cp.async.commit_group;" ::: "memory")
#define CP_WAIT0()  asm volatile("cp.async.wait_group 0;" ::: "memory")

// ===========================================================================
// Merged FFMA2 SGEMM megakernel (verified engine — UNTOUCHED since R8):
//   class E (bid%3==0): hidden = relu(seq[8192,768] @ W1e[768,384] + b1e)
//   class P (else):     pK[z] = ER[1024,768] @ [W1r_top|W1r_bot] (z-th K slice)
// CTA tile 64x128, BK=32, 128 threads.
// ===========================================================================
#define GTM 64
#define GTN 128
#define GTK 32
#define ASTRIDE 68
#define ASTAGE (GTK*ASTRIDE)
#define BSTAGE (GTK*GTN)
#define GEMM_SMEM ((2*ASTAGE + 2*BSTAGE) * 4)   // 50176 bytes

__global__ __launch_bounds__(128) void gemm_mega(
    const float* __restrict__ seq,  const float* __restrict__ W1e,
    const float* __restrict__ b1e,  float* __restrict__ hidden,
    const float* __restrict__ ER,   const float* __restrict__ W1r,
    float* __restrict__ pK)
{
    extern __shared__ float sm[];
    float* smA = sm;
    float* smB = sm + 2 * ASTAGE;

    const int tid = threadIdx.x;
    const int wid = tid >> 5, lane = tid & 31;
    const int lm = lane >> 2;
    const int ln = lane & 3;
    const int col0 = wid * 32 + ln * 8;

    const int bid = blockIdx.x;
    const bool isEnt = (bid % 3) == 0;

    const float* Ab;  int lda;
    const float* Bb;  int ldb;
    float* Cb;        int ldc;
    int CH, bm, colg0;

    if (isEnt) {
        int id = bid / 3;
        int nx = id % 3, my = id / 3;
        bm = my * GTM; colg0 = nx * GTN;
        lda = Hdim; ldb = HH; ldc = HH;
        Ab = seq + (size_t)bm * lda;
        Bb = W1e + colg0;
        Cb = hidden;
        CH = Hdim / GTK;
    } else {
        int id = bid - 1 - (bid - 1) / 3;
        int z = id / 192;
        int rem = id % 192;
        int nx = rem % 12, my = rem / 12;
        bm = my * GTM; colg0 = nx * GTN;
        lda = Hdim; ldb = Hdim; ldc = PAIRN;
        const int Kper = Hdim / ZPAIR;
        Ab = ER + (size_t)z * Kper + (size_t)bm * lda;
        int bn = colg0;
        const float* Bsel = W1r;
        if (bn >= Hdim) { Bsel = W1r + (size_t)Hdim * Hdim; bn -= Hdim; }
        Bb = Bsel + (size_t)z * Kper * ldb + bn;
        Cb = pK + (size_t)z * ((size_t)ME * PAIRN);
        CH = Kper / GTK;
    }

    unsigned long long acc[4][8];
#pragma unroll
    for (int r = 0; r < 4; r++)
#pragma unroll
        for (int c = 0; c < 8; c++) acc[r][c] = 0ull;

    float4 ra[4];

#define LDG_A(k0) do { \
    _Pragma("unroll") \
    for (int q = 0; q < 4; q++) { \
        int idx = q * 128 + tid; \
        int m = idx >> 3, kq = (idx & 7) << 2; \
        ra[q] = *(const float4*)(Ab + (size_t)m * lda + (k0) + kq); \
    } \
} while (0)
#define STS_A(dst) do { \
    _Pragma("unroll") \
    for (int q = 0; q < 4; q++) { \
        int idx = q * 128 + tid; \
        int m = idx >> 3, kq = (idx & 7) << 2; \
        int ms = m ^ kq; \
        (dst)[(kq + 0) * ASTRIDE + ms] = ra[q].x; \
        (dst)[(kq + 1) * ASTRIDE + ms] = ra[q].y; \
        (dst)[(kq + 2) * ASTRIDE + ms] = ra[q].z; \
        (dst)[(kq + 3) * ASTRIDE + ms] = ra[q].w; \
    } \
} while (0)
#define CPA_B(k0, stB) do { \
    uint32_t sb = smem_u32(smB + (stB) * BSTAGE) + (uint32_t)tid * 16u; \
    _Pragma("unroll") \
    for (int q = 0; q < 8; q++) { \
        int idx = q * 128 + tid; \
        int k = idx >> 5, c4 = (idx & 31) << 2; \
        cp_async16(sb + q * 2048u, Bb + (size_t)((k0) + k) * ldb + c4); \
    } \
    CP_COMMIT(); \
} while (0)

    CPA_B(0, 0);
    LDG_A(0);
    STS_A(smA);
    CP_WAIT0();
    __syncthreads();

    for (int c = 0; c < CH; c++) {
        const int st = c & 1;
        const int nx2 = st ^ 1;
        if (c + 1 < CH) {
            CPA_B((c + 1) * GTK, nx2);
            LDG_A((c + 1) * GTK);
        }

        const float* Asm = smA + st * ASTAGE;
        const float* Bsm = smB + st * BSTAGE;
#pragma unroll
        for (int k = 0; k < GTK; k++) {
            const int sw = k & 28;
            ulonglong2 ap0 = *(const ulonglong2*)&Asm[k * ASTRIDE + ((4 * lm) ^ sw)];
            ulonglong2 ap1 = *(const ulonglong2*)&Asm[k * ASTRIDE + (32 + ((4 * lm) ^ sw))];
            float4 b0 = *(const float4*)&Bsm[k * GTN + col0];
            float4 b1 = *(const float4*)&Bsm[k * GTN + col0 + 4];
            unsigned long long bd[8];
            bd[0] = dup2(b0.x); bd[1] = dup2(b0.y); bd[2] = dup2(b0.z); bd[3] = dup2(b0.w);
            bd[4] = dup2(b1.x); bd[5] = dup2(b1.y); bd[6] = dup2(b1.z); bd[7] = dup2(b1.w);
            unsigned long long ap[4] = {ap0.x, ap0.y, ap1.x, ap1.y};
#pragma unroll
            for (int r = 0; r < 4; r++)
#pragma unroll
                for (int cc = 0; cc < 8; cc++)
                    ffma2(acc[r][cc], ap[r], bd[cc]);
        }

        if (c + 1 < CH) STS_A(smA + nx2 * ASTAGE);
        CP_WAIT0();
        __syncthreads();
    }

    const int colg = colg0 + col0;
    float bb[8] = {0, 0, 0, 0, 0, 0, 0, 0};
    if (isEnt) {
        float4 t0 = *(const float4*)(b1e + colg);
        float4 t1 = *(const float4*)(b1e + colg + 4);
        bb[0] = t0.x; bb[1] = t0.y; bb[2] = t0.z; bb[3] = t0.w;
        bb[4] = t1.x; bb[5] = t1.y; bb[6] = t1.z; bb[7] = t1.w;
    }
#pragma unroll
    for (int rp = 0; rp < 4; rp++) {
        int r0 = (rp < 2) ? (4 * lm + 2 * rp) : (32 + 4 * lm + 2 * (rp - 2));
        float lo[8], hi[8];
#pragma unroll
        for (int cc = 0; cc < 8; cc++) {
            float2 v = unpack2(acc[rp][cc]);
            lo[cc] = v.x + bb[cc];
            hi[cc] = v.y + bb[cc];
        }
        if (isEnt) {
#pragma unroll
            for (int q = 0; q < 8; q++) {
                lo[q] = fmaxf(lo[q], 0.f);
                hi[q] = fmaxf(hi[q], 0.f);
            }
        }
        float* C0 = Cb + (size_t)(bm + r0) * ldc + colg;
        float* C1 = Cb + (size_t)(bm + r0 + 1) * ldc + colg;
        *(float4*)C0 = make_float4(lo[0], lo[1], lo[2], lo[3]);
        *(float4*)(C0 + 4) = make_float4(lo[4], lo[5], lo[6], lo[7]);
        *(float4*)C1 = make_float4(hi[0], hi[1], hi[2], hi[3]);
        *(float4*)(C1 + 4) = make_float4(hi[4], hi[5], hi[6], hi[7]);
    }
#undef LDG_A
#undef STS_A
#undef CPA_B
}

// ===========================================================================
// Merged launch 3 (R10 skeleton): EL | combine(+k-pack) | pair-table | Wq.
//  EL: entity_logits = hidden @ W2e + b2e, 256 thr, warp per row (8 rows/blk)
//  combine: v = sum_z pK[z] (+b1r for k'<768), k-paired into g_pA2/g_pB2.
// ===========================================================================
#define ELBLKS (MS / 8)                      // 1024
#define CTBLKS ((PAIRN / 32) * (ME / 32))    // 1536
#define PTBLKS 8                             // 8*256 = 2048 >= NPAIR
#define WQBLKS 18                            // 18*256 = 4608 = 384*12

__global__ __launch_bounds__(256) void el_combine_kernel(
    const float* __restrict__ W2e, const float* __restrict__ b2e,
    const float* __restrict__ b1r, const float* __restrict__ W2r,
    float* __restrict__ el_out)
{
    __shared__ float W2s[HH * ET];           // EL use (13.8 KB)
    __shared__ float t[32][33];              // combine use (4.3 KB)
    const int tid = threadIdx.x;

    if (blockIdx.x < ELBLKS) {
        // ---------------- entity logits ----------------
        for (int i = tid; i < HH * ET; i += 256) W2s[i] = W2e[i];
        __syncthreads();

        const int warp = tid >> 5, lane = tid & 31;
        const int row = blockIdx.x * 8 + warp;
        const float* hrow = g_hidden + (size_t)row * HH;

        float acc[ET];
#pragma unroll
        for (int c = 0; c < ET; c++) acc[c] = 0.f;

#pragma unroll
        for (int kk = 0; kk < HH / 32; kk++) {
            int k = kk * 32 + lane;
            float h = hrow[k];
            const float* w = &W2s[k * ET];
#pragma unroll
            for (int c = 0; c < ET; c++) acc[c] += h * w[c];
        }
#pragma unroll
        for (int c = 0; c < ET; c++)
#pragma unroll
            for (int off = 16; off > 0; off >>= 1)
                acc[c] += __shfl_down_sync(0xffffffffu, acc[c], off);

        if (lane == 0) {
            float* o = el_out + (size_t)row * ET;
#pragma unroll
            for (int c = 0; c < ET; c++) o[c] = acc[c] + b2e[c];
        }
    } else if (blockIdx.x < ELBLKS + CTBLKS) {
        // ---------------- combine + k-paired transpose ----------------
        const int cb = blockIdx.x - ELBLKS;          // 0..1535
        const int kb = (cb % (PAIRN / 32)) * 32;     // k' base
        const int eb = (cb / (PAIRN / 32)) * 32;     // entity-row base
        const int tx = tid & 31;
        const int ty = tid >> 5;                      // 0..7

#pragma unroll
        for (int s = 0; s < 4; s++) {
            int e = eb + ty + s * 8;
            size_t off = (size_t)e * PAIRN + kb + tx;
            float v = g_pK[0][off];
#pragma unroll
            for (int zz = 1; zz < ZPAIR; zz++) v += g_pK[zz][off];
            t[ty + s * 8][tx] = v;
        }
        __syncthreads();

        // thread owns k' = kb + ty*4 + {0..3} at entity e = eb + tx
        const int b = eb >> 6;
        const int n = (eb & 63) + tx;
        float v[4];
#pragma unroll
        for (int s = 0; s < 4; s++) v[s] = t[tx][ty * 4 + s];

        const int kk0 = kb + ty * 4;
        if (kk0 < Hdim) {
#pragma unroll
            for (int s = 0; s < 4; s++) v[s] += b1r[kk0 + s];
            const int k2 = kk0 >> 1;
            g_pA2[((size_t)b * K2 + k2) * Nent + n]     = make_float2(v[0], v[1]);
            g_pA2[((size_t)b * K2 + k2 + 1) * Nent + n] = make_float2(v[2], v[3]);
        } else {
            const int k2 = (kk0 - Hdim) >> 1;
            g_pB2[((size_t)b * K2 + k2) * Nent + n]     = make_float2(v[0], v[1]);
            g_pB2[((size_t)b * K2 + k2 + 1) * Nent + n] = make_float2(v[2], v[3]);
        }
    } else if (blockIdx.x < ELBLKS + CTBLKS + PTBLKS) {
        // ---------------- pair index table ----------------
        int p = (blockIdx.x - ELBLKS - CTBLKS) * 256 + tid;
        if (p < NPAIR) {
            int rem = p, i = 0;
            while (rem >= (Nent - 1) - i) { rem -= (Nent - 1) - i; i++; }
            g_pairs[p * 2]     = i;
            g_pairs[p * 2 + 1] = i + 1 + rem;
        }
    } else {
        // ---------------- Wq[k2][c] = {0.5*W(2k2,c), 0.5*W(2k2+1,c)} ------
        int idx = (blockIdx.x - ELBLKS - CTBLKS - PTBLKS) * 256 + tid;
        if (idx < K2 * 12) {
            int k2 = idx / 12, c = idx % 12;
            float w0 = (c < RT) ? 0.5f * W2r[(2 * k2) * RT + c] : 0.f;
            float w1 = (c < RT) ? 0.5f * W2r[(2 * k2 + 1) * RT + c] : 0.f;
            g_Wq[idx] = make_float2(w0, w1);
        }
    }
}

// ===========================================================================
// Span mean pooling, fixed 16-iteration predicated loop.
// ===========================================================================
__global__ __launch_bounds__(192) void span_pool_kernel(
    const float4* __restrict__ seq4, const int* __restrict__ spans,
    float4* __restrict__ er4)
{
    const int bn = blockIdx.x;
    const int b = bn >> 6;
    const int s0 = spans[bn * 2];
    const int s1 = spans[bn * 2 + 1];
    int cnt = s1 - s0; if (cnt < 1) cnt = 1;
    const float inv = 1.f / (float)cnt;
    const float4* base = seq4 + (size_t)b * Ssz * (Hdim / 4) + threadIdx.x;

    float4 acc = make_float4(0.f, 0.f, 0.f, 0.f);
#pragma unroll
    for (int q = 0; q < 16; q++) {
        int s = s0 + q;
        float4 v = base[(size_t)s * (Hdim / 4)];
        if (s < s1) { acc.x += v.x; acc.y += v.y; acc.z += v.z; acc.w += v.w; }
    }
    acc.x *= inv; acc.y *= inv; acc.z *= inv; acc.w *= inv;
    er4[(size_t)bn * (Hdim / 4) + threadIdx.x] = acc;
}

// ===========================================================================
// relation_logits v5 (R10 shape + R12-validated packed math):
// grid (16, 16), 128 threads = 128 pairs. 12 staged tiles of RK2T=32 k-pairs.
// Packed relu: h2 = x + |x| = 2*relu(x) (exact), W pre-scaled by 0.5.
// Per k2: 2 LDS.64 + 2 fadd2 + LOP + 6 LDS.128 + 12 FFMA2  (23 instr / 2 k)
// ===========================================================================
#define RK2T 32

__global__ __launch_bounds__(128) void relation_kernel(
    const float* __restrict__ b2r, float* __restrict__ out)
{
    __shared__ __align__(16) unsigned long long sA[RK2T * Nent];   // 16 KB
    __shared__ __align__(16) unsigned long long sB[RK2T * Nent];   // 16 KB
    __shared__ __align__(16) unsigned long long sW[RK2T * 12];     // 3 KB

    const int tid = threadIdx.x;
    const int b = blockIdx.y;
    const int p = blockIdx.x * 128 + tid;
    const bool act = (p < NPAIR);
    const int pc = act ? p : 0;
    const int i = g_pairs[pc * 2];
    const int j = g_pairs[pc * 2 + 1];

    const float2* A2 = g_pA2 + (size_t)b * K2 * Nent;
    const float2* B2 = g_pB2 + (size_t)b * K2 * Nent;

    unsigned long long acc[12];
#pragma unroll
    for (int c = 0; c < 12; c++) acc[c] = 0ull;

    const unsigned long long ABSM = 0x7FFFFFFF7FFFFFFFull;

    for (int kt = 0; kt < K2; kt += RK2T) {
        __syncthreads();
        // stage A2/B2 tiles: RK2T*64 float2 = 1024 float4 each, 8/thread
#pragma unroll
        for (int q = 0; q < 8; q++) {
            int idx = q * 128 + tid;
            ((float4*)sA)[idx] = ((const float4*)(A2 + (size_t)kt * Nent))[idx];
            ((float4*)sB)[idx] = ((const float4*)(B2 + (size_t)kt * Nent))[idx];
        }
        // stage Wq tile: RK2T*12 float2 = 192 float4
#pragma unroll
        for (int q = 0; q < 2; q++) {
            int idx = q * 128 + tid;
            if (idx < RK2T * 6)
                ((float4*)sW)[idx] = ((const float4*)(g_Wq + (size_t)kt * 12))[idx];
        }
        __syncthreads();

#pragma unroll 4
        for (int k2 = 0; k2 < RK2T; k2++) {
            unsigned long long a = sA[k2 * Nent + i];
            unsigned long long bq = sB[k2 * Nent + j];
            unsigned long long x = fadd2v(a, bq);
            unsigned long long h2 = fadd2v(x, x & ABSM);   // 2*relu, packed
            const unsigned long long* w = &sW[k2 * 12];
#pragma unroll
            for (int c = 0; c < 12; c++)
                ffma2(acc[c], h2, w[c]);
        }
    }

    if (act) {
        float* dst = out + (size_t)(b * NPAIR + p) * RT;
#pragma unroll
        for (int c = 0; c < RT; c++) {
            float2 v = unpack2(acc[c]);
            dst[c] = v.x + v.y + b2r[c];
        }
    }
}

// ===========================================================================
extern "C" void kernel_launch(void* const* d_in, const int* in_sizes, int n_in,
                              void* d_out, int out_size)
{
    const float* seq   = (const float*)d_in[0];
    const int*   spans = (const int*)d_in[2];
    const float* W1e   = (const float*)d_in[3];
    const float* b1e   = (const float*)d_in[4];
    const float* W2e   = (const float*)d_in[5];
    const float* b2e   = (const float*)d_in[6];
    const float* W1r   = (const float*)d_in[7];
    const float* b1r   = (const float*)d_in[8];
    const float* W2r   = (const float*)d_in[9];
    const float* b2r   = (const float*)d_in[10];

    float* out = (float*)d_out;
    float* EL = out;                                   // [16,512,9]
    float* ER = out + (size_t)MS * ET;                 // [16,64,768]
    float* RL = ER + (size_t)ME * Hdim;                // [16,2016,10]

    void *p_hidden, *p_pK;
    cudaGetSymbolAddress(&p_hidden, g_hidden);
    cudaGetSymbolAddress(&p_pK, g_pK);

    cudaFuncSetAttribute(gemm_mega,
                         cudaFuncAttributeMaxDynamicSharedMemorySize, GEMM_SMEM);

    // 1) entity_repr (output + input of pair GEMM)
    span_pool_kernel<<<Bsz * Nent, 192>>>((const float4*)seq, spans, (float4*)ER);

    // 2) merged GEMMs: hidden (entity) + pK[z] (pair split-K=4), 1152 CTAs
    gemm_mega<<<1152, 128, GEMM_SMEM>>>(
        seq, W1e, b1e, (float*)p_hidden, ER, W1r, (float*)p_pK);

    // 3) entity_logits | combine+k-pack | pair table | Wq pack
    el_combine_kernel<<<ELBLKS + CTBLKS + PTBLKS + WQBLKS, 256>>>(
        W2e, b2e, b1r, W2r, EL);

    // 4) relation_logits (k-paired smem staging)
    relation_kernel<<<dim3((NPAIR + 127) / 128, Bsz), 128>>>(b2r, RL);
}